// round 16
// baseline (speedup 1.0000x reference)
#include <cuda_runtime.h>
#include <cuda_fp16.h>
#include <cstdint>

#define BB 4
#define CC 256
#define HH 256
#define WW 256
#define NROI_MAX 2048
#define FDIM 2304
#define DD 256

typedef __half  fp16;
typedef __half2 fp162;

// ---------------- scratch ----------------------------------------------------
__device__ fp16 g_fmt16[BB * HH * WW * CC];

__device__ fp16 g_x[NROI_MAX * FDIM];

__device__ fp16 g_w1[DD * FDIM];
__device__ fp16 g_w2[DD * DD];
__device__ fp16 g_wc1[DD * DD];
__device__ fp16 g_wi1[DD * DD];
__device__ fp16 g_wr1[DD * DD];
__device__ fp16 g_wc2[DD * DD];
__device__ fp16 g_wi2[DD * DD];
__device__ fp16 g_wr2[DD * DD];

__device__ float g_p0[NROI_MAX * DD];
__device__ float g_p1[NROI_MAX * DD];
__device__ float g_p2[NROI_MAX * DD];
__device__ float g_p3[NROI_MAX * DD];

__device__ fp16 g_h1hi[NROI_MAX * DD],  g_h1lo[NROI_MAX * DD];
__device__ fp16 g_shhi[NROI_MAX * DD],  g_shlo[NROI_MAX * DD];
__device__ fp16 g_t1chi[NROI_MAX * DD], g_t1clo[NROI_MAX * DD];
__device__ fp16 g_t1ihi[NROI_MAX * DD], g_t1ilo[NROI_MAX * DD];
__device__ fp16 g_t1rhi[NROI_MAX * DD], g_t1rlo[NROI_MAX * DD];
__device__ fp16 g_c2hi[NROI_MAX * DD],  g_c2lo[NROI_MAX * DD];
__device__ fp16 g_i2hi[NROI_MAX * DD],  g_i2lo[NROI_MAX * DD];
__device__ fp16 g_r2hi[NROI_MAX * DD],  g_r2lo[NROI_MAX * DD];

__device__ __forceinline__ void split_fp16(float f, fp16& h, fp16& l)
{
    h = __float2half(f);
    l = __float2half(f - __half2float(h));
}

// ---------------- NCHW fp32 -> NHWC fp16 transpose (one batch) ---------------
__global__ __launch_bounds__(256)
void transpose_kernel(const float* __restrict__ fm, fp16* __restrict__ fmt, int b)
{
    __shared__ float tile[64][65];

    const int s0 = blockIdx.x * 64;
    const int c0 = blockIdx.y * 64;
    const int t  = threadIdx.x;

#pragma unroll
    for (int l = 0; l < 4; l++) {
        const int slot = t + l * 256;
        const int ci = slot >> 4;
        const int s4 = (slot & 15) * 4;
        const float4 v = *(const float4*)(fm +
            ((size_t)b * CC + (c0 + ci)) * (size_t)(HH * WW) + s0 + s4);
        tile[ci][s4 + 0] = v.x;
        tile[ci][s4 + 1] = v.y;
        tile[ci][s4 + 2] = v.z;
        tile[ci][s4 + 3] = v.w;
    }
    __syncthreads();

#pragma unroll
    for (int l = 0; l < 4; l++) {
        const int slot = t + l * 256;
        const int si = slot >> 4;
        const int c4 = (slot & 15) * 4;
        fp162 v0 = fp162(__float2half(tile[c4 + 0][si]),
                         __float2half(tile[c4 + 1][si]));
        fp162 v1 = fp162(__float2half(tile[c4 + 2][si]),
                         __float2half(tile[c4 + 3][si]));
        fp162* dst = (fp162*)(fmt + ((size_t)b * (HH * WW) + s0 + si) * (size_t)CC + c0 + c4);
        dst[0] = v0;
        dst[1] = v1;
    }
}

// ---------------- RoIAlignRotated (batch-filtered) ---------------------------
__global__ __launch_bounds__(64)
void roi_kernel(const fp16* __restrict__ fmt,
                const float* __restrict__ boxes,
                const int*   __restrict__ bidx,
                fp16* __restrict__ xout, int bsel)
{
    const int n = blockIdx.x;
    const int b = bidx[n];
    if (b != bsel) return;
    const int t = threadIdx.x;

    __shared__ int   s_o[36][4];
    __shared__ float s_w[36][4];

    if (t < 36) {
        const float gw = (float)(102.4 / 256.0);
        const float bx  = boxes[n*7 + 0];
        const float by  = boxes[n*7 + 1];
        const float rh  = boxes[n*7 + 4] / gw;
        const float rw  = boxes[n*7 + 5] / gw;
        const float ang = boxes[n*7 + 6];

        const float cx = (bx + 51.2f) / gw - 0.5f;
        const float cy = (by + 51.2f) / gw - 0.5f;
        const float ct = cosf(-ang);
        const float st = sinf(-ang);
        const float bin_h = rh / 3.0f;
        const float bin_w = rw / 3.0f;

        const int p  = t;
        const int ph = p / 12;
        const int pw = (p / 4) % 3;
        const int sy = (p >> 1) & 1;
        const int sx = p & 1;

        const float yy = -rh * 0.5f + ((float)ph + ((float)sy + 0.5f) * 0.5f) * bin_h;
        const float xx = -rw * 0.5f + ((float)pw + ((float)sx + 0.5f) * 0.5f) * bin_w;

        float y = yy * ct - xx * st + cy;
        float x = yy * st + xx * ct + cx;

        const bool valid = (y > -1.0f) && (y < (float)HH) && (x > -1.0f) && (x < (float)WW);

        y = fminf(fmaxf(y, 0.0f), (float)(HH - 1));
        x = fminf(fmaxf(x, 0.0f), (float)(WW - 1));

        int y0 = min((int)floorf(y), HH - 1);
        int x0 = min((int)floorf(x), WW - 1);
        int y1 = min(y0 + 1, HH - 1);
        int x1 = min(x0 + 1, WW - 1);

        const float ly = y - (float)y0;
        const float lx = x - (float)x0;
        const float hy = 1.0f - ly;
        const float hx = 1.0f - lx;
        const float v  = valid ? 1.0f : 0.0f;

        s_o[p][0] = (y0 * WW + x0) * CC;
        s_o[p][1] = (y0 * WW + x1) * CC;
        s_o[p][2] = (y1 * WW + x0) * CC;
        s_o[p][3] = (y1 * WW + x1) * CC;
        s_w[p][0] = hy * hx * v;
        s_w[p][1] = hy * lx * v;
        s_w[p][2] = ly * hx * v;
        s_w[p][3] = ly * lx * v;
    }
    __syncthreads();

    const fp16* __restrict__ base = fmt + (size_t)b * (HH * WW) * CC + t * 4;

    float4 acc[9];
#pragma unroll
    for (int i = 0; i < 9; i++) acc[i] = make_float4(0.f, 0.f, 0.f, 0.f);

#pragma unroll
    for (int p = 0; p < 36; p++) {
        const float w0 = s_w[p][0], w1 = s_w[p][1], w2 = s_w[p][2], w3 = s_w[p][3];
        float4& a = acc[p >> 2];
#pragma unroll
        for (int j = 0; j < 4; j++) {
            const fp162* q = (const fp162*)(base + s_o[p][j]);
            const float2 u0 = __half22float2(q[0]);
            const float2 u1 = __half22float2(q[1]);
            const float w = (j == 0) ? w0 : (j == 1) ? w1 : (j == 2) ? w2 : w3;
            a.x += w * u0.x;
            a.y += w * u0.y;
            a.z += w * u1.x;
            a.w += w * u1.y;
        }
    }

    const size_t ob = (size_t)n * FDIM + t * 4;
#pragma unroll
    for (int i = 0; i < 9; i++) {
        fp162 v0 = fp162(__float2half(acc[i].x * 0.25f),
                         __float2half(acc[i].y * 0.25f));
        fp162 v1 = fp162(__float2half(acc[i].z * 0.25f),
                         __float2half(acc[i].w * 0.25f));
        *(fp162*)(xout + ob + i * CC)     = v0;
        *(fp162*)(xout + ob + i * CC + 2) = v1;
    }
}

// ---------------- merged weight convert (fp32 -> fp16) ------------------------
__global__ __launch_bounds__(256)
void wconv_all(const float* __restrict__ w1,
               const float* __restrict__ s0w, const float* __restrict__ s1w,
               const float* __restrict__ s2w, const float* __restrict__ s3w,
               const float* __restrict__ s4w, const float* __restrict__ s5w,
               const float* __restrict__ s6w,
               fp16* __restrict__ w1o,
               fp16* __restrict__ s0o, fp16* __restrict__ s1o,
               fp16* __restrict__ s2o, fp16* __restrict__ s3o,
               fp16* __restrict__ s4o, fp16* __restrict__ s5o,
               fp16* __restrict__ s6o)
{
    const int idx4 = (blockIdx.x * 256 + threadIdx.x) * 4;
    const int W1N = DD * FDIM;

    const float* w; fp16* o; int off;
    if (idx4 < W1N) {
        w = w1; o = w1o; off = idx4;
    } else {
        const int r = idx4 - W1N;
        const int seg = r >> 16;
        off = r & 65535;
        w = (seg == 0) ? s0w : (seg == 1) ? s1w : (seg == 2) ? s2w :
            (seg == 3) ? s3w : (seg == 4) ? s4w : (seg == 5) ? s5w : s6w;
        o = (seg == 0) ? s0o : (seg == 1) ? s1o : (seg == 2) ? s2o :
            (seg == 3) ? s3o : (seg == 4) ? s4o : (seg == 5) ? s5o : s6o;
    }

    const float4 v = *(const float4*)(w + off);
    *(fp162*)(o + off)     = fp162(__float2half(v.x), __float2half(v.y));
    *(fp162*)(o + off + 2) = fp162(__float2half(v.z), __float2half(v.w));
}

// ---------------- combine split-K partials: relu(sum Pi) -> hi/lo -----------
__global__ __launch_bounds__(256)
void combine_relu_split(const float* __restrict__ P0, const float* __restrict__ P1,
                        const float* __restrict__ P2, const float* __restrict__ P3,
                        fp16* __restrict__ Oh, fp16* __restrict__ Ol)
{
    const int off = (blockIdx.x * 256 + threadIdx.x) * 4;
    const float4 a = *(const float4*)(P0 + off);
    const float4 b = *(const float4*)(P1 + off);
    const float4 c = *(const float4*)(P2 + off);
    const float4 d = *(const float4*)(P3 + off);
    float r[4] = {a.x + b.x + c.x + d.x, a.y + b.y + c.y + d.y,
                  a.z + b.z + c.z + d.z, a.w + b.w + c.w + d.w};
    fp16 h[4], l[4];
#pragma unroll
    for (int j = 0; j < 4; j++) {
        r[j] = fmaxf(r[j], 0.0f);
        split_fp16(r[j], h[j], l[j]);
    }
    *(fp162*)(Oh + off)     = fp162(h[0], h[1]);
    *(fp162*)(Oh + off + 2) = fp162(h[2], h[3]);
    *(fp162*)(Ol + off)     = fp162(l[0], l[1]);
    *(fp162*)(Ol + off + 2) = fp162(l[2], l[3]);
}

// ---------------- GEMM common ------------------------------------------------
__device__ __forceinline__ void mma_fp16(float* d, const uint32_t* a, const uint32_t* b)
{
    asm volatile(
        "mma.sync.aligned.m16n8k16.row.col.f32.f16.f16.f32 "
        "{%0,%1,%2,%3}, {%4,%5,%6,%7}, {%8,%9}, {%0,%1,%2,%3};\n"
        : "+f"(d[0]), "+f"(d[1]), "+f"(d[2]), "+f"(d[3])
        : "r"(a[0]), "r"(a[1]), "r"(a[2]), "r"(a[3]), "r"(b[0]), "r"(b[1]));
}

__device__ __forceinline__ void cp_async16(uint32_t smem_addr, const void* gptr)
{
    asm volatile("cp.async.cg.shared.global [%0], [%1], 16;\n"
                 :: "r"(smem_addr), "l"(gptr));
}

#define LDSM4(r, addr) \
    asm volatile("ldmatrix.sync.aligned.m8n8.x4.shared.b16 {%0,%1,%2,%3}, [%4];" \
                 : "=r"((r)[0]), "=r"((r)[1]), "=r"((r)[2]), "=r"((r)[3]) \
                 : "r"(addr))

#define SKB 40
#define PL  (64 * SKB * 2)
#define STAGES 3
#define STB3 (3 * PL)
#define SMEM_G3 (STAGES * STB3)
#define STB2 (2 * PL)
#define SMEM_G2 (STAGES * STB2)

struct GemmCtx {
    uint32_t base, ldOff, aOff, bOff, P16;
    int lrow, ck;
};

__device__ __forceinline__ GemmCtx make_ctx(void* dyn, int tid, int wm, int wn,
                                            uint32_t bplane_off)
{
    GemmCtx cx;
    const int lane = tid & 31;
    cx.base = (uint32_t)__cvta_generic_to_shared(dyn);
    cx.lrow = (tid & 255) >> 2;
    cx.ck   = (tid & 3) * 8;
    cx.ldOff = (uint32_t)((cx.lrow * SKB + cx.ck) * 2);

    const int rowA = wm + (lane & 7) + ((lane >> 3) & 1) * 8;
    const int colA = (lane >> 4) * 8;
    cx.aOff = (uint32_t)((rowA * SKB + colA) * 2);
    const int mB   = lane >> 3;
    const int rowB = wn + (mB >> 1) * 8 + (lane & 7);
    const int colB = (mB & 1) * 8;
    cx.bOff = bplane_off + (uint32_t)((rowB * SKB + colB) * 2);
    cx.P16  = (uint32_t)(16 * SKB) * 2;
    return cx;
}

__device__ __forceinline__ void gemm_mainloop3(
    const fp16* __restrict__ Ah, const fp16* __restrict__ Al,
    const fp16* __restrict__ Bh,
    int m0, int n0, int K, int T,
    const GemmCtx& cx, float acc[2][4][4])
{
    const size_t arow = (size_t)(m0 + cx.lrow) * K + cx.ck;
    const size_t brow = (size_t)(n0 + cx.lrow) * K + cx.ck;

#pragma unroll
    for (int s = 0; s < STAGES - 1; s++) {
        const uint32_t so = (uint32_t)s * STB3;
        const int ko = s << 5;
        cp_async16(cx.base + so + cx.ldOff,          Ah + arow + ko);
        cp_async16(cx.base + so + PL + cx.ldOff,     Al + arow + ko);
        cp_async16(cx.base + so + 2 * PL + cx.ldOff, Bh + brow + ko);
        asm volatile("cp.async.commit_group;\n");
    }

    int cbuf = 0, pbuf = STAGES - 1;
    for (int kt = 0; kt < T; kt++) {
        asm volatile("cp.async.wait_group %0;\n" :: "n"(STAGES - 2));
        __syncthreads();

        if (kt + STAGES - 1 < T) {
            const uint32_t so = (uint32_t)pbuf * STB3;
            const int ko = (kt + STAGES - 1) << 5;
            cp_async16(cx.base + so + cx.ldOff,          Ah + arow + ko);
            cp_async16(cx.base + so + PL + cx.ldOff,     Al + arow + ko);
            cp_async16(cx.base + so + 2 * PL + cx.ldOff, Bh + brow + ko);
        }
        asm volatile("cp.async.commit_group;\n");

        const uint32_t buf = cx.base + (uint32_t)cbuf * STB3;
#pragma unroll
        for (int ks = 0; ks < 32; ks += 16) {
            const uint32_t d = (uint32_t)ks * 2;
            uint32_t ah[4], al[4], b0[4], b1[4];
            LDSM4(ah, buf + cx.aOff + d);
            LDSM4(al, buf + PL + cx.aOff + d);
            LDSM4(b0, buf + cx.bOff + d);
            LDSM4(b1, buf + cx.bOff + cx.P16 + d);

            mma_fp16(acc[0][0], ah, &b0[0]);
            mma_fp16(acc[0][1], ah, &b0[2]);
            mma_fp16(acc[0][2], ah, &b1[0]);
            mma_fp16(acc[0][3], ah, &b1[2]);
            mma_fp16(acc[1][0], al, &b0[0]);
            mma_fp16(acc[1][1], al, &b0[2]);
            mma_fp16(acc[1][2], al, &b1[0]);
            mma_fp16(acc[1][3], al, &b1[2]);
        }

        cbuf = (cbuf + 1 == STAGES) ? 0 : cbuf + 1;
        pbuf = (pbuf + 1 == STAGES) ? 0 : pbuf + 1;
    }
}

__device__ __forceinline__ void gemm_mainloop2(
    const fp16* __restrict__ A, const fp16* __restrict__ B,
    int m0, int n0, int K, int kbase, int T,
    const GemmCtx& cx, float acc[4][4])
{
    const size_t arow = (size_t)(m0 + cx.lrow) * K + kbase + cx.ck;
    const size_t brow = (size_t)(n0 + cx.lrow) * K + kbase + cx.ck;

#pragma unroll
    for (int s = 0; s < STAGES - 1; s++) {
        const uint32_t so = (uint32_t)s * STB2;
        const int ko = s << 5;
        cp_async16(cx.base + so + cx.ldOff,      A + arow + ko);
        cp_async16(cx.base + so + PL + cx.ldOff, B + brow + ko);
        asm volatile("cp.async.commit_group;\n");
    }

    int cbuf = 0, pbuf = STAGES - 1;
    for (int kt = 0; kt < T; kt++) {
        asm volatile("cp.async.wait_group %0;\n" :: "n"(STAGES - 2));
        __syncthreads();

        if (kt + STAGES - 1 < T) {
            const uint32_t so = (uint32_t)pbuf * STB2;
            const int ko = (kt + STAGES - 1) << 5;
            cp_async16(cx.base + so + cx.ldOff,      A + arow + ko);
            cp_async16(cx.base + so + PL + cx.ldOff, B + brow + ko);
        }
        asm volatile("cp.async.commit_group;\n");

        const uint32_t buf = cx.base + (uint32_t)cbuf * STB2;
#pragma unroll
        for (int ks = 0; ks < 32; ks += 16) {
            const uint32_t d = (uint32_t)ks * 2;
            uint32_t a[4], b0[4], b1[4];
            LDSM4(a,  buf + cx.aOff + d);
            LDSM4(b0, buf + cx.bOff + d);
            LDSM4(b1, buf + cx.bOff + cx.P16 + d);

            mma_fp16(acc[0], a, &b0[0]);
            mma_fp16(acc[1], a, &b0[2]);
            mma_fp16(acc[2], a, &b1[0]);
            mma_fp16(acc[3], a, &b1[2]);
        }

        cbuf = (cbuf + 1 == STAGES) ? 0 : cbuf + 1;
        pbuf = (pbuf + 1 == STAGES) ? 0 : pbuf + 1;
    }
}

// ---------------- fused GEMM (z selects head; relu+split epilogue) -----------
__global__ __launch_bounds__(256)
void gemm_heads(const fp16* __restrict__ Ah0, const fp16* __restrict__ Ah1,
                const fp16* __restrict__ Ah2,
                const fp16* __restrict__ Al0, const fp16* __restrict__ Al1,
                const fp16* __restrict__ Al2,
                const fp16* __restrict__ B0, const fp16* __restrict__ B1,
                const fp16* __restrict__ B2,
                fp16* __restrict__ Ch0, fp16* __restrict__ Ch1,
                fp16* __restrict__ Ch2,
                fp16* __restrict__ Cl0, fp16* __restrict__ Cl1,
                fp16* __restrict__ Cl2,
                int N, int K)
{
    const int bz = blockIdx.z;
    const fp16* Ah = (bz == 0) ? Ah0 : ((bz == 1) ? Ah1 : Ah2);
    const fp16* Al = (bz == 0) ? Al0 : ((bz == 1) ? Al1 : Al2);
    const fp16* Bh = (bz == 0) ? B0  : ((bz == 1) ? B1  : B2);
    fp16* Ch       = (bz == 0) ? Ch0 : ((bz == 1) ? Ch1 : Ch2);
    fp16* Cl       = (bz == 0) ? Cl0 : ((bz == 1) ? Cl1 : Cl2);

    extern __shared__ __align__(16) char dyn[];
    const int tid  = threadIdx.x;
    const int warp = tid >> 5;
    const int lane = tid & 31;
    const int g    = lane >> 2;
    const int tg   = lane & 3;
    const int m0 = blockIdx.y * 64;
    const int n0 = blockIdx.x * 64;
    const int wm = (warp >> 1) * 16;
    const int wn = (warp & 1) * 32;

    GemmCtx cx = make_ctx(dyn, tid, wm, wn, 2 * PL);

    float acc[2][4][4];
#pragma unroll
    for (int p = 0; p < 2; p++)
#pragma unroll
        for (int nt = 0; nt < 4; nt++)
#pragma unroll
            for (int i = 0; i < 4; i++) acc[p][nt][i] = 0.0f;

    gemm_mainloop3(Ah, Al, Bh, m0, n0, K, K >> 5, cx, acc);

    const int r0 = m0 + wm + g;
    const int r1 = r0 + 8;
#pragma unroll
    for (int nt = 0; nt < 4; nt++) {
        const int col = n0 + wn + nt * 8 + 2 * tg;
        float s0 = fmaxf(acc[0][nt][0] + acc[1][nt][0], 0.0f);
        float s1 = fmaxf(acc[0][nt][1] + acc[1][nt][1], 0.0f);
        float s2 = fmaxf(acc[0][nt][2] + acc[1][nt][2], 0.0f);
        float s3 = fmaxf(acc[0][nt][3] + acc[1][nt][3], 0.0f);
        fp16 h0, l0, h1_, l1, h2, l2, h3, l3;
        split_fp16(s0, h0, l0); split_fp16(s1, h1_, l1);
        split_fp16(s2, h2, l2); split_fp16(s3, h3, l3);
        *(fp162*)&Ch[(size_t)r0 * N + col] = fp162(h0, h1_);
        *(fp162*)&Cl[(size_t)r0 * N + col] = fp162(l0, l1);
        *(fp162*)&Ch[(size_t)r1 * N + col] = fp162(h2, h3);
        *(fp162*)&Cl[(size_t)r1 * N + col] = fp162(l2, l3);
    }
}

// ---------------- single-pass split-K GEMM (trunk1) --------------------------
__global__ __launch_bounds__(256)
void gemm_splitk1(const fp16* __restrict__ A, const fp16* __restrict__ B,
                  float* __restrict__ P0, float* __restrict__ P1,
                  float* __restrict__ P2, float* __restrict__ P3,
                  int N, int K, int Ksplit)
{
    const int bz = blockIdx.z;
    float* P = (bz == 0) ? P0 : ((bz == 1) ? P1 : ((bz == 2) ? P2 : P3));
    const int kbase = bz * Ksplit;

    extern __shared__ __align__(16) char dyn[];
    const int tid  = threadIdx.x;
    const int warp = tid >> 5;
    const int lane = tid & 31;
    const int g    = lane >> 2;
    const int tg   = lane & 3;
    const int m0 = blockIdx.y * 64;
    const int n0 = blockIdx.x * 64;
    const int wm = (warp >> 1) * 16;
    const int wn = (warp & 1) * 32;

    GemmCtx cx = make_ctx(dyn, tid, wm, wn, PL);

    float acc[4][4];
#pragma unroll
    for (int nt = 0; nt < 4; nt++)
#pragma unroll
        for (int i = 0; i < 4; i++) acc[nt][i] = 0.0f;

    gemm_mainloop2(A, B, m0, n0, K, kbase, Ksplit >> 5, cx, acc);

    const int r0 = m0 + wm + g;
    const int r1 = r0 + 8;
#pragma unroll
    for (int nt = 0; nt < 4; nt++) {
        const int col = n0 + wn + nt * 8 + 2 * tg;
        *(float2*)&P[(size_t)r0 * N + col] = make_float2(acc[nt][0], acc[nt][1]);
        *(float2*)&P[(size_t)r1 * N + col] = make_float2(acc[nt][2], acc[nt][3]);
    }
}

// ---------------- fused head-final projections -----------------------------
__global__ void head_final(const fp16* __restrict__ c2h, const fp16* __restrict__ c2l,
                           const fp16* __restrict__ i2h, const fp16* __restrict__ i2l,
                           const fp16* __restrict__ r2h, const fp16* __restrict__ r2l,
                           const float* __restrict__ wc, const float* __restrict__ bc,
                           const float* __restrict__ wi, const float* __restrict__ bi,
                           const float* __restrict__ wr, const float* __restrict__ br,
                           float* __restrict__ out, int N)
{
    const int warp = (blockIdx.x * blockDim.x + threadIdx.x) >> 5;
    const int lane = threadIdx.x & 31;
    if (warp >= N) return;

    float sc = 0.0f, si = 0.0f;
    float sr[7];
#pragma unroll
    for (int j = 0; j < 7; j++) sr[j] = 0.0f;

    const size_t base = (size_t)warp * DD;

#pragma unroll
    for (int kk = 0; kk < DD / 32; kk++) {
        const int k = lane + kk * 32;
        const float vc = __half2float(c2h[base + k]) + __half2float(c2l[base + k]);
        const float vi = __half2float(i2h[base + k]) + __half2float(i2l[base + k]);
        const float vr = __half2float(r2h[base + k]) + __half2float(r2l[base + k]);
        sc += vc * wc[k];
        si += vi * wi[k];
#pragma unroll
        for (int j = 0; j < 7; j++) sr[j] += vr * wr[j * DD + k];
    }

#pragma unroll
    for (int off = 16; off > 0; off >>= 1) {
        sc += __shfl_down_sync(0xffffffffu, sc, off);
        si += __shfl_down_sync(0xffffffffu, si, off);
#pragma unroll
        for (int j = 0; j < 7; j++) sr[j] += __shfl_down_sync(0xffffffffu, sr[j], off);
    }

    if (lane == 0) {
        out[warp]     = sc + bc[0];
        out[N + warp] = si + bi[0];
#pragma unroll
        for (int j = 0; j < 7; j++)
            out[2 * N + warp * 7 + j] = sr[j] + br[j];
    }
}

// ---------------- launch ----------------------------------------------------
extern "C" void kernel_launch(void* const* d_in, const int* in_sizes, int n_in,
                              void* d_out, int out_size)
{
    const float* fm    = (const float*)d_in[0];
    const float* boxes = (const float*)d_in[1];
    const int*   bidx  = (const int*)  d_in[2];
    const float* w_sh1 = (const float*)d_in[3];
    const float* w_sh2 = (const float*)d_in[4];
    const float* w_c1  = (const float*)d_in[5];
    const float* w_c2  = (const float*)d_in[6];
    const float* w_c3  = (const float*)d_in[7];
    const float* b_c3  = (const float*)d_in[8];
    const float* w_i1  = (const float*)d_in[9];
    const float* w_i2  = (const float*)d_in[10];
    const float* w_i3  = (const float*)d_in[11];
    const float* b_i3  = (const float*)d_in[12];
    const float* w_r1  = (const float*)d_in[13];
    const float* w_r2  = (const float*)d_in[14];
    const float* w_r3  = (const float*)d_in[15];
    const float* b_r3  = (const float*)d_in[16];
    float* out = (float*)d_out;

    const int N = in_sizes[2];

    float *pp0, *pp1, *pp2, *pp3;
    cudaGetSymbolAddress((void**)&pp0,  g_p0);
    cudaGetSymbolAddress((void**)&pp1,  g_p1);
    cudaGetSymbolAddress((void**)&pp2,  g_p2);
    cudaGetSymbolAddress((void**)&pp3,  g_p3);

#define SYM(p, s) fp16* p; cudaGetSymbolAddress((void**)&p, s)
    SYM(pfmt, g_fmt16);
    SYM(px, g_x);
    SYM(pw1, g_w1);
    SYM(pw2, g_w2);
    SYM(pwc1, g_wc1);  SYM(pwi1, g_wi1);  SYM(pwr1, g_wr1);
    SYM(pwc2, g_wc2);  SYM(pwi2, g_wi2);  SYM(pwr2, g_wr2);
    SYM(ph1h, g_h1hi);  SYM(ph1l, g_h1lo);
    SYM(pshh, g_shhi);  SYM(pshl, g_shlo);
    SYM(pt1ch, g_t1chi); SYM(pt1cl, g_t1clo);
    SYM(pt1ih, g_t1ihi); SYM(pt1il, g_t1ilo);
    SYM(pt1rh, g_t1rhi); SYM(pt1rl, g_t1rlo);
    SYM(pc2h, g_c2hi);  SYM(pc2l, g_c2lo);
    SYM(pi2h, g_i2hi);  SYM(pi2l, g_i2lo);
    SYM(pr2h, g_r2hi);  SYM(pr2l, g_r2lo);
#undef SYM

    cudaFuncSetAttribute(gemm_heads,
                         cudaFuncAttributeMaxDynamicSharedMemorySize, SMEM_G3);
    cudaFuncSetAttribute(gemm_splitk1,
                         cudaFuncAttributeMaxDynamicSharedMemorySize, SMEM_G2);

    // side stream + events (created once; host-side objects, no device alloc)
    static cudaStream_t s2 = nullptr;
    static cudaEvent_t evFork = nullptr, evT[BB], evJoin = nullptr;
    if (s2 == nullptr) {
        cudaStreamCreateWithFlags(&s2, cudaStreamNonBlocking);
        cudaEventCreateWithFlags(&evFork, cudaEventDisableTiming);
        cudaEventCreateWithFlags(&evJoin, cudaEventDisableTiming);
        for (int b = 0; b < BB; b++)
            cudaEventCreateWithFlags(&evT[b], cudaEventDisableTiming);
    }

    // fork side stream into the captured graph
    cudaEventRecord(evFork, 0);
    cudaStreamWaitEvent(s2, evFork, 0);

    // 0a) weight converts on side stream (independent of transpose)
    {
        const int total = DD * FDIM + 7 * DD * DD;
        wconv_all<<<total / 1024, 256, 0, s2>>>(
            w_sh1, w_sh2, w_c1, w_i1, w_r1, w_c2, w_i2, w_r2,
            pw1, pw2, pwc1, pwi1, pwr1, pwc2, pwi2, pwr2);
    }

    // 0b) per-batch transpose on main stream; roi(b) on side stream after evT[b]
    {
        dim3 grid(HH * WW / 64, CC / 64, 1);
        for (int b = 0; b < BB; b++) {
            transpose_kernel<<<grid, 256>>>(fm, pfmt, b);
            cudaEventRecord(evT[b], 0);
            cudaStreamWaitEvent(s2, evT[b], 0);
            roi_kernel<<<N, 64, 0, s2>>>(pfmt, boxes, bidx, px, b);
        }
    }

    // join: main stream waits for all side-stream work
    cudaEventRecord(evJoin, s2);
    cudaStreamWaitEvent(0, evJoin, 0);

    // 2) trunk GEMM 1 (single-pass fp16, split-K = 4 x 576) + combine
    {
        dim3 grid(DD / 64, N / 64, 4);
        gemm_splitk1<<<grid, 256, SMEM_G2>>>(px, pw1,
                                             pp0, pp1, pp2, pp3,
                                             DD, FDIM, FDIM / 4);
        combine_relu_split<<<N * DD / 1024, 256>>>(pp0, pp1, pp2, pp3,
                                                   ph1h, ph1l);
    }

    // 3) trunk GEMM 2 (2-pass hi/lo, fused relu+split epilogue)
    {
        dim3 grid(DD / 64, N / 64, 1);
        gemm_heads<<<grid, 256, SMEM_G3>>>(
            ph1h, ph1h, ph1h, ph1l, ph1l, ph1l,
            pw2, pw2, pw2,
            pshh, pshh, pshh, pshl, pshl, pshl,
            DD, DD);
    }

    // 4) heads, batched over z=3
    dim3 grid3(DD / 64, N / 64, 3);
    gemm_heads<<<grid3, 256, SMEM_G3>>>(
        pshh, pshh, pshh, pshl, pshl, pshl,
        pwc1, pwi1, pwr1,
        pt1ch, pt1ih, pt1rh, pt1cl, pt1il, pt1rl,
        DD, DD);
    gemm_heads<<<grid3, 256, SMEM_G3>>>(
        pt1ch, pt1ih, pt1rh, pt1cl, pt1il, pt1rl,
        pwc2, pwi2, pwr2,
        pc2h, pi2h, pr2h, pc2l, pi2l, pr2l,
        DD, DD);

    // 5) final projections
    {
        const int threads = 256;
        const int blocks = (N * 32 + threads - 1) / threads;
        head_final<<<blocks, threads>>>(pc2h, pc2l, pi2h, pi2l, pr2h, pr2l,
                                        w_c3, b_c3, w_i3, b_i3, w_r3, b_r3,
                                        out, N);
    }
}

// round 17
// speedup vs baseline: 1.2449x; 1.2449x over previous
#include <cuda_runtime.h>
#include <cuda_fp16.h>
#include <cstdint>

#define BB 4
#define CC 256
#define HH 256
#define WW 256
#define NROI_MAX 2048
#define FDIM 2304
#define DD 256

typedef __half  fp16;
typedef __half2 fp162;

// ---------------- scratch ----------------------------------------------------
__device__ fp16 g_fmt16[BB * HH * WW * CC];

__device__ fp16 g_x[NROI_MAX * FDIM];

__device__ fp16 g_w1[DD * FDIM];
__device__ fp16 g_w2[DD * DD];
__device__ fp16 g_wc1[DD * DD];
__device__ fp16 g_wi1[DD * DD];
__device__ fp16 g_wr1[DD * DD];
__device__ fp16 g_wc2[DD * DD];
__device__ fp16 g_wi2[DD * DD];
__device__ fp16 g_wr2[DD * DD];

__device__ float g_p0[NROI_MAX * DD];
__device__ float g_p1[NROI_MAX * DD];
__device__ float g_p2[NROI_MAX * DD];
__device__ float g_p3[NROI_MAX * DD];

__device__ fp16 g_h1hi[NROI_MAX * DD],  g_h1lo[NROI_MAX * DD];
__device__ fp16 g_shhi[NROI_MAX * DD],  g_shlo[NROI_MAX * DD];
__device__ fp16 g_t1chi[NROI_MAX * DD], g_t1clo[NROI_MAX * DD];
__device__ fp16 g_t1ihi[NROI_MAX * DD], g_t1ilo[NROI_MAX * DD];
__device__ fp16 g_t1rhi[NROI_MAX * DD], g_t1rlo[NROI_MAX * DD];
__device__ fp16 g_c2hi[NROI_MAX * DD],  g_c2lo[NROI_MAX * DD];
__device__ fp16 g_i2hi[NROI_MAX * DD],  g_i2lo[NROI_MAX * DD];
__device__ fp16 g_r2hi[NROI_MAX * DD],  g_r2lo[NROI_MAX * DD];

__device__ __forceinline__ void split_fp16(float f, fp16& h, fp16& l)
{
    h = __float2half(f);
    l = __float2half(f - __half2float(h));
}

// ---------------- NCHW fp32 -> NHWC fp16 transpose (64c x 64s) ---------------
// Store phase: 16B stores (8 channels per thread per slot).
__global__ __launch_bounds__(256)
void transpose_kernel(const float* __restrict__ fm, fp16* __restrict__ fmt)
{
    __shared__ float tile[64][65];

    const int b  = blockIdx.z;
    const int s0 = blockIdx.x * 64;
    const int c0 = blockIdx.y * 64;
    const int t  = threadIdx.x;

#pragma unroll
    for (int l = 0; l < 4; l++) {
        const int slot = t + l * 256;
        const int ci = slot >> 4;
        const int s4 = (slot & 15) * 4;
        const float4 v = *(const float4*)(fm +
            ((size_t)b * CC + (c0 + ci)) * (size_t)(HH * WW) + s0 + s4);
        tile[ci][s4 + 0] = v.x;
        tile[ci][s4 + 1] = v.y;
        tile[ci][s4 + 2] = v.z;
        tile[ci][s4 + 3] = v.w;
    }
    __syncthreads();

#pragma unroll
    for (int l = 0; l < 2; l++) {
        const int slot = t + l * 256;       // 512 slots = 64 si x 8 c-groups
        const int si = slot >> 3;           // 0..63
        const int c8 = (slot & 7) * 8;      // 0..56
        fp162 v[4];
#pragma unroll
        for (int j = 0; j < 4; j++)
            v[j] = fp162(__float2half(tile[c8 + 2 * j][si]),
                         __float2half(tile[c8 + 2 * j + 1][si]));
        *(float4*)(fmt + ((size_t)b * (HH * WW) + s0 + si) * (size_t)CC + c0 + c8) =
            *(float4*)v;
    }
}

// ---------------- RoIAlignRotated (NHWC fp16 gather, writes fp16 x) ----------
__global__ __launch_bounds__(64)
void roi_kernel(const fp16* __restrict__ fmt,
                const float* __restrict__ boxes,
                const int*   __restrict__ bidx,
                fp16* __restrict__ xout)
{
    const int n = blockIdx.x;
    const int t = threadIdx.x;

    __shared__ int   s_o[36][4];
    __shared__ float s_w[36][4];

    if (t < 36) {
        const float gw = (float)(102.4 / 256.0);
        const float bx  = boxes[n*7 + 0];
        const float by  = boxes[n*7 + 1];
        const float rh  = boxes[n*7 + 4] / gw;
        const float rw  = boxes[n*7 + 5] / gw;
        const float ang = boxes[n*7 + 6];

        const float cx = (bx + 51.2f) / gw - 0.5f;
        const float cy = (by + 51.2f) / gw - 0.5f;
        const float ct = cosf(-ang);
        const float st = sinf(-ang);
        const float bin_h = rh / 3.0f;
        const float bin_w = rw / 3.0f;

        const int p  = t;
        const int ph = p / 12;
        const int pw = (p / 4) % 3;
        const int sy = (p >> 1) & 1;
        const int sx = p & 1;

        const float yy = -rh * 0.5f + ((float)ph + ((float)sy + 0.5f) * 0.5f) * bin_h;
        const float xx = -rw * 0.5f + ((float)pw + ((float)sx + 0.5f) * 0.5f) * bin_w;

        float y = yy * ct - xx * st + cy;
        float x = yy * st + xx * ct + cx;

        const bool valid = (y > -1.0f) && (y < (float)HH) && (x > -1.0f) && (x < (float)WW);

        y = fminf(fmaxf(y, 0.0f), (float)(HH - 1));
        x = fminf(fmaxf(x, 0.0f), (float)(WW - 1));

        int y0 = min((int)floorf(y), HH - 1);
        int x0 = min((int)floorf(x), WW - 1);
        int y1 = min(y0 + 1, HH - 1);
        int x1 = min(x0 + 1, WW - 1);

        const float ly = y - (float)y0;
        const float lx = x - (float)x0;
        const float hy = 1.0f - ly;
        const float hx = 1.0f - lx;
        const float v  = valid ? 1.0f : 0.0f;

        s_o[p][0] = (y0 * WW + x0) * CC;
        s_o[p][1] = (y0 * WW + x1) * CC;
        s_o[p][2] = (y1 * WW + x0) * CC;
        s_o[p][3] = (y1 * WW + x1) * CC;
        s_w[p][0] = hy * hx * v;
        s_w[p][1] = hy * lx * v;
        s_w[p][2] = ly * hx * v;
        s_w[p][3] = ly * lx * v;
    }
    __syncthreads();

    const int b = bidx[n];
    const fp16* __restrict__ base = fmt + (size_t)b * (HH * WW) * CC + t * 4;

    float4 acc[9];
#pragma unroll
    for (int i = 0; i < 9; i++) acc[i] = make_float4(0.f, 0.f, 0.f, 0.f);

#pragma unroll
    for (int p = 0; p < 36; p++) {
        const float w0 = s_w[p][0], w1 = s_w[p][1], w2 = s_w[p][2], w3 = s_w[p][3];
        float4& a = acc[p >> 2];
#pragma unroll
        for (int j = 0; j < 4; j++) {
            const fp162* q = (const fp162*)(base + s_o[p][j]);
            const float2 u0 = __half22float2(q[0]);
            const float2 u1 = __half22float2(q[1]);
            const float w = (j == 0) ? w0 : (j == 1) ? w1 : (j == 2) ? w2 : w3;
            a.x += w * u0.x;
            a.y += w * u0.y;
            a.z += w * u1.x;
            a.w += w * u1.y;
        }
    }

    const size_t ob = (size_t)n * FDIM + t * 4;
#pragma unroll
    for (int i = 0; i < 9; i++) {
        fp162 v0 = fp162(__float2half(acc[i].x * 0.25f),
                         __float2half(acc[i].y * 0.25f));
        fp162 v1 = fp162(__float2half(acc[i].z * 0.25f),
                         __float2half(acc[i].w * 0.25f));
        *(fp162*)(xout + ob + i * CC)     = v0;
        *(fp162*)(xout + ob + i * CC + 2) = v1;
    }
}

// ---------------- merged weight convert (fp32 -> fp16) ------------------------
__global__ __launch_bounds__(256)
void wconv_all(const float* __restrict__ w1,
               const float* __restrict__ s0w, const float* __restrict__ s1w,
               const float* __restrict__ s2w, const float* __restrict__ s3w,
               const float* __restrict__ s4w, const float* __restrict__ s5w,
               const float* __restrict__ s6w,
               fp16* __restrict__ w1o,
               fp16* __restrict__ s0o, fp16* __restrict__ s1o,
               fp16* __restrict__ s2o, fp16* __restrict__ s3o,
               fp16* __restrict__ s4o, fp16* __restrict__ s5o,
               fp16* __restrict__ s6o)
{
    const int idx4 = (blockIdx.x * 256 + threadIdx.x) * 4;
    const int W1N = DD * FDIM;

    const float* w; fp16* o; int off;
    if (idx4 < W1N) {
        w = w1; o = w1o; off = idx4;
    } else {
        const int r = idx4 - W1N;
        const int seg = r >> 16;
        off = r & 65535;
        w = (seg == 0) ? s0w : (seg == 1) ? s1w : (seg == 2) ? s2w :
            (seg == 3) ? s3w : (seg == 4) ? s4w : (seg == 5) ? s5w : s6w;
        o = (seg == 0) ? s0o : (seg == 1) ? s1o : (seg == 2) ? s2o :
            (seg == 3) ? s3o : (seg == 4) ? s4o : (seg == 5) ? s5o : s6o;
    }

    const float4 v = *(const float4*)(w + off);
    *(fp162*)(o + off)     = fp162(__float2half(v.x), __float2half(v.y));
    *(fp162*)(o + off + 2) = fp162(__float2half(v.z), __float2half(v.w));
}

// ---------------- combine split-K partials: relu(sum Pi) -> hi/lo -----------
__global__ __launch_bounds__(256)
void combine_relu_split(const float* __restrict__ P0, const float* __restrict__ P1,
                        const float* __restrict__ P2, const float* __restrict__ P3,
                        fp16* __restrict__ Oh, fp16* __restrict__ Ol)
{
    const int off = (blockIdx.x * 256 + threadIdx.x) * 4;
    const float4 a = *(const float4*)(P0 + off);
    const float4 b = *(const float4*)(P1 + off);
    const float4 c = *(const float4*)(P2 + off);
    const float4 d = *(const float4*)(P3 + off);
    float r[4] = {a.x + b.x + c.x + d.x, a.y + b.y + c.y + d.y,
                  a.z + b.z + c.z + d.z, a.w + b.w + c.w + d.w};
    fp16 h[4], l[4];
#pragma unroll
    for (int j = 0; j < 4; j++) {
        r[j] = fmaxf(r[j], 0.0f);
        split_fp16(r[j], h[j], l[j]);
    }
    *(fp162*)(Oh + off)     = fp162(h[0], h[1]);
    *(fp162*)(Oh + off + 2) = fp162(h[2], h[3]);
    *(fp162*)(Ol + off)     = fp162(l[0], l[1]);
    *(fp162*)(Ol + off + 2) = fp162(l[2], l[3]);
}

// ---------------- GEMM common ------------------------------------------------
__device__ __forceinline__ void mma_fp16(float* d, const uint32_t* a, const uint32_t* b)
{
    asm volatile(
        "mma.sync.aligned.m16n8k16.row.col.f32.f16.f16.f32 "
        "{%0,%1,%2,%3}, {%4,%5,%6,%7}, {%8,%9}, {%0,%1,%2,%3};\n"
        : "+f"(d[0]), "+f"(d[1]), "+f"(d[2]), "+f"(d[3])
        : "r"(a[0]), "r"(a[1]), "r"(a[2]), "r"(a[3]), "r"(b[0]), "r"(b[1]));
}

__device__ __forceinline__ void cp_async16(uint32_t smem_addr, const void* gptr)
{
    asm volatile("cp.async.cg.shared.global [%0], [%1], 16;\n"
                 :: "r"(smem_addr), "l"(gptr));
}

#define LDSM4(r, addr) \
    asm volatile("ldmatrix.sync.aligned.m8n8.x4.shared.b16 {%0,%1,%2,%3}, [%4];" \
                 : "=r"((r)[0]), "=r"((r)[1]), "=r"((r)[2]), "=r"((r)[3]) \
                 : "r"(addr))

#define SKB 40
#define PL  (64 * SKB * 2)
#define STAGES 3
#define STB3 (3 * PL)
#define SMEM_G3 (STAGES * STB3)
#define STB2 (2 * PL)
#define SMEM_G2 (STAGES * STB2)

struct GemmCtx {
    uint32_t base, ldOff, aOff, bOff, P16;
    int lrow, ck;
};

__device__ __forceinline__ GemmCtx make_ctx(void* dyn, int tid, int wm, int wn,
                                            uint32_t bplane_off)
{
    GemmCtx cx;
    const int lane = tid & 31;
    cx.base = (uint32_t)__cvta_generic_to_shared(dyn);
    cx.lrow = (tid & 255) >> 2;
    cx.ck   = (tid & 3) * 8;
    cx.ldOff = (uint32_t)((cx.lrow * SKB + cx.ck) * 2);

    const int rowA = wm + (lane & 7) + ((lane >> 3) & 1) * 8;
    const int colA = (lane >> 4) * 8;
    cx.aOff = (uint32_t)((rowA * SKB + colA) * 2);
    const int mB   = lane >> 3;
    const int rowB = wn + (mB >> 1) * 8 + (lane & 7);
    const int colB = (mB & 1) * 8;
    cx.bOff = bplane_off + (uint32_t)((rowB * SKB + colB) * 2);
    cx.P16  = (uint32_t)(16 * SKB) * 2;
    return cx;
}

__device__ __forceinline__ void gemm_mainloop3(
    const fp16* __restrict__ Ah, const fp16* __restrict__ Al,
    const fp16* __restrict__ Bh,
    int m0, int n0, int K, int T,
    const GemmCtx& cx, float acc[2][4][4])
{
    const size_t arow = (size_t)(m0 + cx.lrow) * K + cx.ck;
    const size_t brow = (size_t)(n0 + cx.lrow) * K + cx.ck;

#pragma unroll
    for (int s = 0; s < STAGES - 1; s++) {
        const uint32_t so = (uint32_t)s * STB3;
        const int ko = s << 5;
        cp_async16(cx.base + so + cx.ldOff,          Ah + arow + ko);
        cp_async16(cx.base + so + PL + cx.ldOff,     Al + arow + ko);
        cp_async16(cx.base + so + 2 * PL + cx.ldOff, Bh + brow + ko);
        asm volatile("cp.async.commit_group;\n");
    }

    int cbuf = 0, pbuf = STAGES - 1;
    for (int kt = 0; kt < T; kt++) {
        asm volatile("cp.async.wait_group %0;\n" :: "n"(STAGES - 2));
        __syncthreads();

        if (kt + STAGES - 1 < T) {
            const uint32_t so = (uint32_t)pbuf * STB3;
            const int ko = (kt + STAGES - 1) << 5;
            cp_async16(cx.base + so + cx.ldOff,          Ah + arow + ko);
            cp_async16(cx.base + so + PL + cx.ldOff,     Al + arow + ko);
            cp_async16(cx.base + so + 2 * PL + cx.ldOff, Bh + brow + ko);
        }
        asm volatile("cp.async.commit_group;\n");

        const uint32_t buf = cx.base + (uint32_t)cbuf * STB3;
#pragma unroll
        for (int ks = 0; ks < 32; ks += 16) {
            const uint32_t d = (uint32_t)ks * 2;
            uint32_t ah[4], al[4], b0[4], b1[4];
            LDSM4(ah, buf + cx.aOff + d);
            LDSM4(al, buf + PL + cx.aOff + d);
            LDSM4(b0, buf + cx.bOff + d);
            LDSM4(b1, buf + cx.bOff + cx.P16 + d);

            mma_fp16(acc[0][0], ah, &b0[0]);
            mma_fp16(acc[0][1], ah, &b0[2]);
            mma_fp16(acc[0][2], ah, &b1[0]);
            mma_fp16(acc[0][3], ah, &b1[2]);
            mma_fp16(acc[1][0], al, &b0[0]);
            mma_fp16(acc[1][1], al, &b0[2]);
            mma_fp16(acc[1][2], al, &b1[0]);
            mma_fp16(acc[1][3], al, &b1[2]);
        }

        cbuf = (cbuf + 1 == STAGES) ? 0 : cbuf + 1;
        pbuf = (pbuf + 1 == STAGES) ? 0 : pbuf + 1;
    }
}

__device__ __forceinline__ void gemm_mainloop2(
    const fp16* __restrict__ A, const fp16* __restrict__ B,
    int m0, int n0, int K, int kbase, int T,
    const GemmCtx& cx, float acc[4][4])
{
    const size_t arow = (size_t)(m0 + cx.lrow) * K + kbase + cx.ck;
    const size_t brow = (size_t)(n0 + cx.lrow) * K + kbase + cx.ck;

#pragma unroll
    for (int s = 0; s < STAGES - 1; s++) {
        const uint32_t so = (uint32_t)s * STB2;
        const int ko = s << 5;
        cp_async16(cx.base + so + cx.ldOff,      A + arow + ko);
        cp_async16(cx.base + so + PL + cx.ldOff, B + brow + ko);
        asm volatile("cp.async.commit_group;\n");
    }

    int cbuf = 0, pbuf = STAGES - 1;
    for (int kt = 0; kt < T; kt++) {
        asm volatile("cp.async.wait_group %0;\n" :: "n"(STAGES - 2));
        __syncthreads();

        if (kt + STAGES - 1 < T) {
            const uint32_t so = (uint32_t)pbuf * STB2;
            const int ko = (kt + STAGES - 1) << 5;
            cp_async16(cx.base + so + cx.ldOff,      A + arow + ko);
            cp_async16(cx.base + so + PL + cx.ldOff, B + brow + ko);
        }
        asm volatile("cp.async.commit_group;\n");

        const uint32_t buf = cx.base + (uint32_t)cbuf * STB2;
#pragma unroll
        for (int ks = 0; ks < 32; ks += 16) {
            const uint32_t d = (uint32_t)ks * 2;
            uint32_t a[4], b0[4], b1[4];
            LDSM4(a,  buf + cx.aOff + d);
            LDSM4(b0, buf + cx.bOff + d);
            LDSM4(b1, buf + cx.bOff + cx.P16 + d);

            mma_fp16(acc[0], a, &b0[0]);
            mma_fp16(acc[1], a, &b0[2]);
            mma_fp16(acc[2], a, &b1[0]);
            mma_fp16(acc[3], a, &b1[2]);
        }

        cbuf = (cbuf + 1 == STAGES) ? 0 : cbuf + 1;
        pbuf = (pbuf + 1 == STAGES) ? 0 : pbuf + 1;
    }
}

// ---------------- fused GEMM (z selects head; relu+split epilogue) -----------
__global__ __launch_bounds__(256)
void gemm_heads(const fp16* __restrict__ Ah0, const fp16* __restrict__ Ah1,
                const fp16* __restrict__ Ah2,
                const fp16* __restrict__ Al0, const fp16* __restrict__ Al1,
                const fp16* __restrict__ Al2,
                const fp16* __restrict__ B0, const fp16* __restrict__ B1,
                const fp16* __restrict__ B2,
                fp16* __restrict__ Ch0, fp16* __restrict__ Ch1,
                fp16* __restrict__ Ch2,
                fp16* __restrict__ Cl0, fp16* __restrict__ Cl1,
                fp16* __restrict__ Cl2,
                int N, int K)
{
    const int bz = blockIdx.z;
    const fp16* Ah = (bz == 0) ? Ah0 : ((bz == 1) ? Ah1 : Ah2);
    const fp16* Al = (bz == 0) ? Al0 : ((bz == 1) ? Al1 : Al2);
    const fp16* Bh = (bz == 0) ? B0  : ((bz == 1) ? B1  : B2);
    fp16* Ch       = (bz == 0) ? Ch0 : ((bz == 1) ? Ch1 : Ch2);
    fp16* Cl       = (bz == 0) ? Cl0 : ((bz == 1) ? Cl1 : Cl2);

    extern __shared__ __align__(16) char dyn[];
    const int tid  = threadIdx.x;
    const int warp = tid >> 5;
    const int lane = tid & 31;
    const int g    = lane >> 2;
    const int tg   = lane & 3;
    const int m0 = blockIdx.y * 64;
    const int n0 = blockIdx.x * 64;
    const int wm = (warp >> 1) * 16;
    const int wn = (warp & 1) * 32;

    GemmCtx cx = make_ctx(dyn, tid, wm, wn, 2 * PL);

    float acc[2][4][4];
#pragma unroll
    for (int p = 0; p < 2; p++)
#pragma unroll
        for (int nt = 0; nt < 4; nt++)
#pragma unroll
            for (int i = 0; i < 4; i++) acc[p][nt][i] = 0.0f;

    gemm_mainloop3(Ah, Al, Bh, m0, n0, K, K >> 5, cx, acc);

    const int r0 = m0 + wm + g;
    const int r1 = r0 + 8;
#pragma unroll
    for (int nt = 0; nt < 4; nt++) {
        const int col = n0 + wn + nt * 8 + 2 * tg;
        float s0 = fmaxf(acc[0][nt][0] + acc[1][nt][0], 0.0f);
        float s1 = fmaxf(acc[0][nt][1] + acc[1][nt][1], 0.0f);
        float s2 = fmaxf(acc[0][nt][2] + acc[1][nt][2], 0.0f);
        float s3 = fmaxf(acc[0][nt][3] + acc[1][nt][3], 0.0f);
        fp16 h0, l0, h1_, l1, h2, l2, h3, l3;
        split_fp16(s0, h0, l0); split_fp16(s1, h1_, l1);
        split_fp16(s2, h2, l2); split_fp16(s3, h3, l3);
        *(fp162*)&Ch[(size_t)r0 * N + col] = fp162(h0, h1_);
        *(fp162*)&Cl[(size_t)r0 * N + col] = fp162(l0, l1);
        *(fp162*)&Ch[(size_t)r1 * N + col] = fp162(h2, h3);
        *(fp162*)&Cl[(size_t)r1 * N + col] = fp162(l2, l3);
    }
}

// ---------------- single-pass split-K GEMM (trunk1) --------------------------
__global__ __launch_bounds__(256)
void gemm_splitk1(const fp16* __restrict__ A, const fp16* __restrict__ B,
                  float* __restrict__ P0, float* __restrict__ P1,
                  float* __restrict__ P2, float* __restrict__ P3,
                  int N, int K, int Ksplit)
{
    const int bz = blockIdx.z;
    float* P = (bz == 0) ? P0 : ((bz == 1) ? P1 : ((bz == 2) ? P2 : P3));
    const int kbase = bz * Ksplit;

    extern __shared__ __align__(16) char dyn[];
    const int tid  = threadIdx.x;
    const int warp = tid >> 5;
    const int lane = tid & 31;
    const int g    = lane >> 2;
    const int tg   = lane & 3;
    const int m0 = blockIdx.y * 64;
    const int n0 = blockIdx.x * 64;
    const int wm = (warp >> 1) * 16;
    const int wn = (warp & 1) * 32;

    GemmCtx cx = make_ctx(dyn, tid, wm, wn, PL);

    float acc[4][4];
#pragma unroll
    for (int nt = 0; nt < 4; nt++)
#pragma unroll
        for (int i = 0; i < 4; i++) acc[nt][i] = 0.0f;

    gemm_mainloop2(A, B, m0, n0, K, kbase, Ksplit >> 5, cx, acc);

    const int r0 = m0 + wm + g;
    const int r1 = r0 + 8;
#pragma unroll
    for (int nt = 0; nt < 4; nt++) {
        const int col = n0 + wn + nt * 8 + 2 * tg;
        *(float2*)&P[(size_t)r0 * N + col] = make_float2(acc[nt][0], acc[nt][1]);
        *(float2*)&P[(size_t)r1 * N + col] = make_float2(acc[nt][2], acc[nt][3]);
    }
}

// ---------------- fused head-final projections -----------------------------
__global__ void head_final(const fp16* __restrict__ c2h, const fp16* __restrict__ c2l,
                           const fp16* __restrict__ i2h, const fp16* __restrict__ i2l,
                           const fp16* __restrict__ r2h, const fp16* __restrict__ r2l,
                           const float* __restrict__ wc, const float* __restrict__ bc,
                           const float* __restrict__ wi, const float* __restrict__ bi,
                           const float* __restrict__ wr, const float* __restrict__ br,
                           float* __restrict__ out, int N)
{
    const int warp = (blockIdx.x * blockDim.x + threadIdx.x) >> 5;
    const int lane = threadIdx.x & 31;
    if (warp >= N) return;

    float sc = 0.0f, si = 0.0f;
    float sr[7];
#pragma unroll
    for (int j = 0; j < 7; j++) sr[j] = 0.0f;

    const size_t base = (size_t)warp * DD;

#pragma unroll
    for (int kk = 0; kk < DD / 32; kk++) {
        const int k = lane + kk * 32;
        const float vc = __half2float(c2h[base + k]) + __half2float(c2l[base + k]);
        const float vi = __half2float(i2h[base + k]) + __half2float(i2l[base + k]);
        const float vr = __half2float(r2h[base + k]) + __half2float(r2l[base + k]);
        sc += vc * wc[k];
        si += vi * wi[k];
#pragma unroll
        for (int j = 0; j < 7; j++) sr[j] += vr * wr[j * DD + k];
    }

#pragma unroll
    for (int off = 16; off > 0; off >>= 1) {
        sc += __shfl_down_sync(0xffffffffu, sc, off);
        si += __shfl_down_sync(0xffffffffu, si, off);
#pragma unroll
        for (int j = 0; j < 7; j++) sr[j] += __shfl_down_sync(0xffffffffu, sr[j], off);
    }

    if (lane == 0) {
        out[warp]     = sc + bc[0];
        out[N + warp] = si + bi[0];
#pragma unroll
        for (int j = 0; j < 7; j++)
            out[2 * N + warp * 7 + j] = sr[j] + br[j];
    }
}

// ---------------- launch ----------------------------------------------------
extern "C" void kernel_launch(void* const* d_in, const int* in_sizes, int n_in,
                              void* d_out, int out_size)
{
    const float* fm    = (const float*)d_in[0];
    const float* boxes = (const float*)d_in[1];
    const int*   bidx  = (const int*)  d_in[2];
    const float* w_sh1 = (const float*)d_in[3];
    const float* w_sh2 = (const float*)d_in[4];
    const float* w_c1  = (const float*)d_in[5];
    const float* w_c2  = (const float*)d_in[6];
    const float* w_c3  = (const float*)d_in[7];
    const float* b_c3  = (const float*)d_in[8];
    const float* w_i1  = (const float*)d_in[9];
    const float* w_i2  = (const float*)d_in[10];
    const float* w_i3  = (const float*)d_in[11];
    const float* b_i3  = (const float*)d_in[12];
    const float* w_r1  = (const float*)d_in[13];
    const float* w_r2  = (const float*)d_in[14];
    const float* w_r3  = (const float*)d_in[15];
    const float* b_r3  = (const float*)d_in[16];
    float* out = (float*)d_out;

    const int N = in_sizes[2];

    float *pp0, *pp1, *pp2, *pp3;
    cudaGetSymbolAddress((void**)&pp0,  g_p0);
    cudaGetSymbolAddress((void**)&pp1,  g_p1);
    cudaGetSymbolAddress((void**)&pp2,  g_p2);
    cudaGetSymbolAddress((void**)&pp3,  g_p3);

#define SYM(p, s) fp16* p; cudaGetSymbolAddress((void**)&p, s)
    SYM(pfmt, g_fmt16);
    SYM(px, g_x);
    SYM(pw1, g_w1);
    SYM(pw2, g_w2);
    SYM(pwc1, g_wc1);  SYM(pwi1, g_wi1);  SYM(pwr1, g_wr1);
    SYM(pwc2, g_wc2);  SYM(pwi2, g_wi2);  SYM(pwr2, g_wr2);
    SYM(ph1h, g_h1hi);  SYM(ph1l, g_h1lo);
    SYM(pshh, g_shhi);  SYM(pshl, g_shlo);
    SYM(pt1ch, g_t1chi); SYM(pt1cl, g_t1clo);
    SYM(pt1ih, g_t1ihi); SYM(pt1il, g_t1ilo);
    SYM(pt1rh, g_t1rhi); SYM(pt1rl, g_t1rlo);
    SYM(pc2h, g_c2hi);  SYM(pc2l, g_c2lo);
    SYM(pi2h, g_i2hi);  SYM(pi2l, g_i2lo);
    SYM(pr2h, g_r2hi);  SYM(pr2l, g_r2lo);
#undef SYM

    cudaFuncSetAttribute(gemm_heads,
                         cudaFuncAttributeMaxDynamicSharedMemorySize, SMEM_G3);
    cudaFuncSetAttribute(gemm_splitk1,
                         cudaFuncAttributeMaxDynamicSharedMemorySize, SMEM_G2);

    // 0a) merged weight converts (fp32 -> fp16)
    {
        const int total = DD * FDIM + 7 * DD * DD;
        wconv_all<<<total / 1024, 256>>>(
            w_sh1, w_sh2, w_c1, w_i1, w_r1, w_c2, w_i2, w_r2,
            pw1, pw2, pwc1, pwi1, pwr1, pwc2, pwi2, pwr2);
    }

    // 0b) NCHW fp32 -> NHWC fp16
    {
        dim3 grid(HH * WW / 64, CC / 64, BB);
        transpose_kernel<<<grid, 256>>>(fm, pfmt);
    }

    // 1) RoIAlignRotated -> x fp16 [N, 2304]
    roi_kernel<<<N, 64>>>(pfmt, boxes, bidx, px);

    // 2) trunk GEMM 1 (single-pass fp16, split-K = 4 x 576) + combine
    {
        dim3 grid(DD / 64, N / 64, 4);
        gemm_splitk1<<<grid, 256, SMEM_G2>>>(px, pw1,
                                             pp0, pp1, pp2, pp3,
                                             DD, FDIM, FDIM / 4);
        combine_relu_split<<<N * DD / 1024, 256>>>(pp0, pp1, pp2, pp3,
                                                   ph1h, ph1l);
    }

    // 3) trunk GEMM 2 (2-pass hi/lo, fused relu+split epilogue)
    {
        dim3 grid(DD / 64, N / 64, 1);
        gemm_heads<<<grid, 256, SMEM_G3>>>(
            ph1h, ph1h, ph1h, ph1l, ph1l, ph1l,
            pw2, pw2, pw2,
            pshh, pshh, pshh, pshl, pshl, pshl,
            DD, DD);
    }

    // 4) heads, batched over z=3
    dim3 grid3(DD / 64, N / 64, 3);
    gemm_heads<<<grid3, 256, SMEM_G3>>>(
        pshh, pshh, pshh, pshl, pshl, pshl,
        pwc1, pwi1, pwr1,
        pt1ch, pt1ih, pt1rh, pt1cl, pt1il, pt1rl,
        DD, DD);
    gemm_heads<<<grid3, 256, SMEM_G3>>>(
        pt1ch, pt1ih, pt1rh, pt1cl, pt1il, pt1rl,
        pwc2, pwi2, pwr2,
        pc2h, pi2h, pr2h, pc2l, pi2l, pr2l,
        DD, DD);

    // 5) final projections
    {
        const int threads = 256;
        const int blocks = (N * 32 + threads - 1) / threads;
        head_final<<<blocks, threads>>>(pc2h, pc2l, pi2h, pi2l, pr2h, pr2l,
                                        w_c3, b_c3, w_i3, b_i3, w_r3, b_r3,
                                        out, N);
    }
}